// round 7
// baseline (speedup 1.0000x reference)
#include <cuda_runtime.h>

typedef unsigned long long ull;

// ---- SoA weight planes ----
__device__ __align__(16) float g_w1c[16],  g_w1s[16];    // [co*4 + i*2 + j]
__device__ __align__(16) float g_w2c[544], g_w2s[544];   // [co*68 + c*16 + i*4 + j]
__device__ __align__(16) float4 g_wfq[2880];             // [o*288 + f] = (c, s, s, c)

__global__ void prep_kernel(const float* __restrict__ w1,
                            const float* __restrict__ w2,
                            const float* __restrict__ wf) {
    int t = threadIdx.x;
    if (t < 16) {
        float s, c; sincosf(w1[t], &s, &c);
        g_w1c[t] = c; g_w1s[t] = s;
    }
    for (int i = t; i < 512; i += blockDim.x) {
        int co = i >> 6, r = i & 63;
        float s, c; sincosf(w2[i], &s, &c);
        g_w2c[co * 68 + r] = c; g_w2s[co * 68 + r] = s;
    }
    for (int i = t; i < 2880; i += blockDim.x) {
        int f = i / 10, o = i % 10;
        float s, c; sincosf(wf[i], &s, &c);
        g_wfq[o * 288 + f] = make_float4(c, s, s, c);
    }
}

// packed dual-FMA: acc(lo,hi) += a(lo,hi) * b(lo,hi)
static __device__ __forceinline__ void ffma2(ull& acc, ull a, ull b) {
    asm("fma.rn.f32x2 %0, %1, %2, %0;" : "+l"(acc) : "l"(a), "l"(b));
}
static __device__ __forceinline__ float f2lo(ull v) { return __uint_as_float((unsigned)v); }
static __device__ __forceinline__ float f2hi(ull v) { return __uint_as_float((unsigned)(v >> 32)); }

// MUFU-free sincos: quadrant reduction + minimax polys
static __device__ __forceinline__ void fast_sincos(float x, float& s, float& c) {
    float t = fmaf(x, 0.63661977236758134f, 12582912.0f);
    unsigned q = __float_as_uint(t);
    float kf = t - 12582912.0f;
    float r = fmaf(kf, -1.57079625129699707031f, x);
    r = fmaf(kf, -7.54978941586159e-08f, r);
    float y = r * r;
    float ps = fmaf(y, -1.95152959e-4f, 8.33216087e-3f);
    ps = fmaf(y, ps, -1.66666546e-1f);
    float s0 = fmaf(r * y, ps, r);
    float pc = fmaf(y, 2.44331571e-5f, -1.38873162e-3f);
    pc = fmaf(y, pc, 4.16666232e-2f);
    pc = fmaf(y, pc, -0.5f);
    float c0 = fmaf(y, pc, 1.0f);
    bool sw = q & 1u;
    float ss = sw ? c0 : s0;
    float cc = sw ? s0 : c0;
    unsigned sgs = (q & 2u) << 30;
    unsigned sgc = ((q + 1u) & 2u) << 30;
    s = __uint_as_float(__float_as_uint(ss) ^ sgs);
    c = __uint_as_float(__float_as_uint(cc) ^ sgc);
}

// MUFU-free rsqrt
static __device__ __forceinline__ float fast_rsqrt(float d) {
    float y = __uint_as_float(0x5F3759DFu - (__float_as_uint(d) >> 1));
    float h = 0.5f * d;
    y = y * fmaf(-(h * y), y, 1.5f);
    y = y * fmaf(-(h * y), y, 1.5f);
    return y;
}

#define GRID_BLOCKS 592   // 148 SMs * 4 resident blocks: one wave, persistent

__global__ __launch_bounds__(320, 4) void ring_kernel(const float* __restrict__ x,
                                                      float* __restrict__ out, int nimg) {
    // pixel planes (28x28), row stride 28
    __shared__ __align__(16) float s_pxc[784], s_pxs[784];
    // conv1 planes [c*224 + row*16 + pos], copy A at pos, copy B shifted by -2
    __shared__ __align__(16) float s_h1cA[896], s_h1cB[896];
    __shared__ __align__(16) float s_h1sA[896], s_h1sB[896];
    __shared__ __align__(16) float2 s_h2[288];               // [(ho*6+wo)*8 + co]
    __shared__ __align__(16) float s_w1c[16],  s_w1s[16];
    __shared__ __align__(16) float s_w2c[544], s_w2s[544];

    const int tid = threadIdx.x;

    // ---- once per block: stage weights ----
    if (tid < 16) { s_w1c[tid] = g_w1c[tid]; s_w1s[tid] = g_w1s[tid]; }
    for (int i = tid; i < 544; i += 320) { s_w2c[i] = g_w2c[i]; s_w2s[i] = g_w2s[i]; }
    // (first __syncthreads happens inside the loop before stage 1 reads weights)

    for (int img = blockIdx.x; img < nimg; img += GRID_BLOCKS) {
        // ---- Stage 0: pixel trig -> SoA planes (STS.128 per 4 pixels) ----
        const float4* xb4 = reinterpret_cast<const float4*>(x + (size_t)img * 784);
        for (int i = tid; i < 196; i += 320) {
            float4 v = xb4[i];
            float s0, c0, s1, c1, s2, c2, s3, c3;
            fast_sincos(v.x, s0, c0);
            fast_sincos(v.y, s1, c1);
            fast_sincos(v.z, s2, c2);
            fast_sincos(v.w, s3, c3);
            *reinterpret_cast<float4*>(&s_pxc[4 * i]) = make_float4(c0, c1, c2, c3);
            *reinterpret_cast<float4*>(&s_pxs[4 * i]) = make_float4(s0, s1, s2, s3);
        }
        __syncthreads();   // px ready (and weights, on first iteration)

        // ---- Stage 1: conv1 2x2 s2 -> 14x14x4; one spatial pos/thread, 4 co ----
        if (tid < 196) {
            int py = tid / 14, px = tid % 14;
            int base = py * 56 + px * 2;
            ull vc0 = *(const ull*)&s_pxc[base];
            ull vc1 = *(const ull*)&s_pxc[base + 28];
            ull vs0 = *(const ull*)&s_pxs[base];
            ull vs1 = *(const ull*)&s_pxs[base + 28];
            int dst = py * 16 + px;
#pragma unroll
            for (int co = 0; co < 4; co++) {
                ulonglong2 wc = *(const ulonglong2*)&s_w1c[co * 4];
                ulonglong2 ws = *(const ulonglong2*)&s_w1s[co * 4];
                ull S = 0, T3 = 0, T4 = 0;
                ffma2(S,  vc0, wc.x); ffma2(S,  vc1, wc.y);
                ffma2(S,  vs0, ws.x); ffma2(S,  vs1, ws.y);
                ffma2(T3, vs0, wc.x); ffma2(T3, vs1, wc.y);
                ffma2(T4, vc0, ws.x); ffma2(T4, vc1, ws.y);
                float Sx = f2lo(S) + f2hi(S);
                float Sy = (f2lo(T3) + f2hi(T3)) - (f2lo(T4) + f2hi(T4));
                float r = fast_rsqrt(fmaxf(Sx * Sx + Sy * Sy, 1e-30f));
                float hc = Sx * r, hs = Sy * r;
                int d = co * 224 + dst;
                s_h1cA[d] = hc; s_h1sA[d] = hs;
                if (px >= 2) { s_h1cB[d - 2] = hc; s_h1sB[d - 2] = hs; }
            }
        }
        __syncthreads();   // h1 ready

        // ---- Stage 2: conv2 4x4 s2 -> 288 outputs; one output/thread, all LDS.128 ----
        int st = tid + ((img & 3) << 5);       // rotate idle warp across SMSPs
        if (st >= 320) st -= 320;
        if (st < 288) {
            int co = st & 7, sp = st >> 3;     // co fastest -> broadcast in 8-lane groups
            int ho = sp / 6, wo = sp % 6;
            const float* pc = (wo & 1) ? s_h1cB : s_h1cA;
            const float* ps = (wo & 1) ? s_h1sB : s_h1sA;
            const int vb0 = ho * 32 + (wo & ~1) * 2;   // aligned window start
            const int wb0 = co * 68;
            ull S = 0, T3 = 0, T4 = 0;
#pragma unroll
            for (int c = 0; c < 4; c++) {
#pragma unroll
                for (int i = 0; i < 4; i++) {
                    int vb = c * 224 + vb0 + i * 16;
                    ulonglong2 vc = *(const ulonglong2*)&pc[vb];
                    ulonglong2 vs = *(const ulonglong2*)&ps[vb];
                    int wb = wb0 + c * 16 + i * 4;
                    ulonglong2 wc = *(const ulonglong2*)&s_w2c[wb];
                    ulonglong2 ws = *(const ulonglong2*)&s_w2s[wb];
                    ffma2(S,  vc.x, wc.x); ffma2(S,  vc.y, wc.y);
                    ffma2(S,  vs.x, ws.x); ffma2(S,  vs.y, ws.y);
                    ffma2(T3, vs.x, wc.x); ffma2(T3, vs.y, wc.y);
                    ffma2(T4, vc.x, ws.x); ffma2(T4, vc.y, ws.y);
                }
            }
            float Sx = f2lo(S) + f2hi(S);
            float Sy = (f2lo(T3) + f2hi(T3)) - (f2lo(T4) + f2hi(T4));
            float r = fast_rsqrt(fmaxf(Sx * Sx + Sy * Sy, 1e-30f));
            s_h2[st] = make_float2(Sx * r, Sy * r);
        }
        __syncthreads();   // h2 ready

        // ---- Stage 3: FF ring, one warp per class; wf float4 from global (L1-hot) ----
        int o = tid >> 5, lane = tid & 31;
        const float4* wfo = g_wfq + o * 288;
        ull S = 0, T = 0;
#pragma unroll
        for (int f = lane, k = 0; k < 9; k++, f += 32) {
            ull a = *(const ull*)&s_h2[f];
            float4 w = __ldg(wfo + f);
            ull wlo, whi;
            asm("mov.b64 %0, {%2, %3}; mov.b64 %1, {%4, %5};"
                : "=l"(wlo), "=l"(whi) : "f"(w.x), "f"(w.y), "f"(w.z), "f"(w.w));
            ffma2(S, a, wlo);   // (c*wc, s*ws)
            ffma2(T, a, whi);   // (c*ws, s*wc)
        }
        float Sx = f2lo(S) + f2hi(S);
        float Sy = f2hi(T) - f2lo(T);
#pragma unroll
        for (int off = 16; off; off >>= 1) {
            Sx += __shfl_xor_sync(0xffffffff, Sx, off);
            Sy += __shfl_xor_sync(0xffffffff, Sy, off);
        }
        if (lane == 0)
            out[(size_t)img * 10 + o] = Sy * fast_rsqrt(fmaxf(Sx * Sx + Sy * Sy, 1e-30f));
        // no barrier: next stage-0 writes px planes (stage-1 consumers passed
        // them before the h1 barrier); next stage-2 write of h2 happens only
        // after the next h1 barrier, by which point every warp finished stage 3.
    }
}

extern "C" void kernel_launch(void* const* d_in, const int* in_sizes, int n_in,
                              void* d_out, int out_size) {
    const float* x  = (const float*)d_in[0];
    const float* w1 = (const float*)d_in[1];
    const float* w2 = (const float*)d_in[2];
    const float* wf = (const float*)d_in[3];
    float* out = (float*)d_out;
    int B = in_sizes[0] / 784;
    prep_kernel<<<1, 512>>>(w1, w2, wf);
    ring_kernel<<<GRID_BLOCKS, 320>>>(x, out, B);
}

// round 8
// speedup vs baseline: 1.0435x; 1.0435x over previous
#include <cuda_runtime.h>

typedef unsigned long long ull;

// ---- SoA weight planes ----
__device__ __align__(16) float g_w1c[16],  g_w1s[16];    // [co*4 + i*2 + j]
__device__ __align__(16) float g_w2c[544], g_w2s[544];   // [co*68 + c*16 + i*4 + j]
__device__ __align__(16) float4 g_wfq[2880];             // [o*288 + f] = (c, s, s, c)

__global__ void prep_kernel(const float* __restrict__ w1,
                            const float* __restrict__ w2,
                            const float* __restrict__ wf) {
    int gt = blockIdx.x * blockDim.x + threadIdx.x;   // 0..3071, 3408 jobs
    for (int i = gt; i < 3408; i += gridDim.x * blockDim.x) {
        if (i < 16) {
            float s, c; sincosf(w1[i], &s, &c);
            g_w1c[i] = c; g_w1s[i] = s;
        } else if (i < 528) {
            int k = i - 16;
            int co = k >> 6, r = k & 63;
            float s, c; sincosf(w2[k], &s, &c);
            g_w2c[co * 68 + r] = c; g_w2s[co * 68 + r] = s;
        } else {
            int k = i - 528;
            int f = k / 10, o = k % 10;
            float s, c; sincosf(wf[k], &s, &c);
            g_wfq[o * 288 + f] = make_float4(c, s, s, c);
        }
    }
}

// packed dual-FMA: acc(lo,hi) += a(lo,hi) * b(lo,hi)
static __device__ __forceinline__ void ffma2(ull& acc, ull a, ull b) {
    asm("fma.rn.f32x2 %0, %1, %2, %0;" : "+l"(acc) : "l"(a), "l"(b));
}
static __device__ __forceinline__ float f2lo(ull v) { return __uint_as_float((unsigned)v); }
static __device__ __forceinline__ float f2hi(ull v) { return __uint_as_float((unsigned)(v >> 32)); }

// MUFU-free sincos: quadrant reduction + minimax polys
static __device__ __forceinline__ void fast_sincos(float x, float& s, float& c) {
    float t = fmaf(x, 0.63661977236758134f, 12582912.0f);
    unsigned q = __float_as_uint(t);
    float kf = t - 12582912.0f;
    float r = fmaf(kf, -1.57079625129699707031f, x);
    r = fmaf(kf, -7.54978941586159e-08f, r);
    float y = r * r;
    float ps = fmaf(y, -1.95152959e-4f, 8.33216087e-3f);
    ps = fmaf(y, ps, -1.66666546e-1f);
    float s0 = fmaf(r * y, ps, r);
    float pc = fmaf(y, 2.44331571e-5f, -1.38873162e-3f);
    pc = fmaf(y, pc, 4.16666232e-2f);
    pc = fmaf(y, pc, -0.5f);
    float c0 = fmaf(y, pc, 1.0f);
    bool sw = q & 1u;
    float ss = sw ? c0 : s0;
    float cc = sw ? s0 : c0;
    unsigned sgs = (q & 2u) << 30;
    unsigned sgc = ((q + 1u) & 2u) << 30;
    s = __uint_as_float(__float_as_uint(ss) ^ sgs);
    c = __uint_as_float(__float_as_uint(cc) ^ sgc);
}

// MUFU-free rsqrt
static __device__ __forceinline__ float fast_rsqrt(float d) {
    float y = __uint_as_float(0x5F3759DFu - (__float_as_uint(d) >> 1));
    float h = 0.5f * d;
    y = y * fmaf(-(h * y), y, 1.5f);
    y = y * fmaf(-(h * y), y, 1.5f);
    return y;
}

__global__ __launch_bounds__(320, 4) void ring_kernel(const float* __restrict__ x,
                                                      float* __restrict__ out) {
    __shared__ __align__(16) float s_pxc[784], s_pxs[784];       // pixel planes, 28x28
    // conv1 planes [c*224 + row*16 + pos]; copy A at pos, copy B shifted by -2
    __shared__ __align__(16) float s_h1cA[896], s_h1cB[896];
    __shared__ __align__(16) float s_h1sA[896], s_h1sB[896];
    __shared__ __align__(16) float2 s_h2[288];                   // [(ho*6+wo)*8 + co]
    __shared__ __align__(16) float s_w1c[16],  s_w1s[16];
    __shared__ __align__(16) float s_w2c[544], s_w2s[544];

    const int tid = threadIdx.x;

    // ---- Stage 0: pixel trig -> SoA planes + weight staging ----
    const float4* xb4 = reinterpret_cast<const float4*>(x + (size_t)blockIdx.x * 784);
    for (int i = tid; i < 196; i += 320) {
        float4 v = xb4[i];
        float s0, c0, s1, c1, s2, c2, s3, c3;
        fast_sincos(v.x, s0, c0);
        fast_sincos(v.y, s1, c1);
        fast_sincos(v.z, s2, c2);
        fast_sincos(v.w, s3, c3);
        *reinterpret_cast<float4*>(&s_pxc[4 * i]) = make_float4(c0, c1, c2, c3);
        *reinterpret_cast<float4*>(&s_pxs[4 * i]) = make_float4(s0, s1, s2, s3);
    }
    if (tid < 16) { s_w1c[tid] = g_w1c[tid]; s_w1s[tid] = g_w1s[tid]; }
    for (int i = tid; i < 544; i += 320) { s_w2c[i] = g_w2c[i]; s_w2s[i] = g_w2s[i]; }
    __syncthreads();

    // ---- Stage 1: conv1 2x2 s2 -> 14x14x4; one spatial pos/thread, 4 co ----
    if (tid < 196) {
        int py = tid / 14, px = tid % 14;
        int base = py * 56 + px * 2;
        ull vc0 = *(const ull*)&s_pxc[base];
        ull vc1 = *(const ull*)&s_pxc[base + 28];
        ull vs0 = *(const ull*)&s_pxs[base];
        ull vs1 = *(const ull*)&s_pxs[base + 28];
        int dst = py * 16 + px;
#pragma unroll
        for (int co = 0; co < 4; co++) {
            ulonglong2 wc = *(const ulonglong2*)&s_w1c[co * 4];
            ulonglong2 ws = *(const ulonglong2*)&s_w1s[co * 4];
            ull S = 0, T3 = 0, T4 = 0;
            ffma2(S,  vc0, wc.x); ffma2(S,  vc1, wc.y);
            ffma2(S,  vs0, ws.x); ffma2(S,  vs1, ws.y);
            ffma2(T3, vs0, wc.x); ffma2(T3, vs1, wc.y);
            ffma2(T4, vc0, ws.x); ffma2(T4, vc1, ws.y);
            float Sx = f2lo(S) + f2hi(S);
            float Sy = (f2lo(T3) + f2hi(T3)) - (f2lo(T4) + f2hi(T4));
            float r = fast_rsqrt(fmaxf(Sx * Sx + Sy * Sy, 1e-30f));
            float hc = Sx * r, hs = Sy * r;
            int d = co * 224 + dst;
            s_h1cA[d] = hc; s_h1sA[d] = hs;
            if (px >= 2) { s_h1cB[d - 2] = hc; s_h1sB[d - 2] = hs; }
        }
    }
    __syncthreads();

    // ---- Stage 2: conv2 4x4 s2 -> 288 outputs; one output/thread, all LDS.128 ----
    int st = tid + ((blockIdx.x & 3) << 5);   // rotate idle warp across SMSPs
    if (st >= 320) st -= 320;
    if (st < 288) {
        int co = st & 7, sp = st >> 3;        // co fastest -> broadcast in 8-lane groups
        int ho = sp / 6, wo = sp % 6;
        const float* pc = (wo & 1) ? s_h1cB : s_h1cA;
        const float* ps = (wo & 1) ? s_h1sB : s_h1sA;
        const int vb0 = ho * 32 + (wo & ~1) * 2;   // 16B-aligned window start
        const int wb0 = co * 68;
        ull S = 0, T3 = 0, T4 = 0;
#pragma unroll
        for (int c = 0; c < 4; c++) {
#pragma unroll
            for (int i = 0; i < 4; i++) {
                int vb = c * 224 + vb0 + i * 16;
                ulonglong2 vc = *(const ulonglong2*)&pc[vb];
                ulonglong2 vs = *(const ulonglong2*)&ps[vb];
                int wb = wb0 + c * 16 + i * 4;
                ulonglong2 wc = *(const ulonglong2*)&s_w2c[wb];
                ulonglong2 ws = *(const ulonglong2*)&s_w2s[wb];
                ffma2(S,  vc.x, wc.x); ffma2(S,  vc.y, wc.y);
                ffma2(S,  vs.x, ws.x); ffma2(S,  vs.y, ws.y);
                ffma2(T3, vs.x, wc.x); ffma2(T3, vs.y, wc.y);
                ffma2(T4, vc.x, ws.x); ffma2(T4, vc.y, ws.y);
            }
        }
        float Sx = f2lo(S) + f2hi(S);
        float Sy = (f2lo(T3) + f2hi(T3)) - (f2lo(T4) + f2hi(T4));
        float r = fast_rsqrt(fmaxf(Sx * Sx + Sy * Sy, 1e-30f));
        s_h2[st] = make_float2(Sx * r, Sy * r);
    }
    __syncthreads();

    // ---- Stage 3: FF ring, one warp per class; wf float4 from global (L1/L2-hot) ----
    int o = tid >> 5, lane = tid & 31;
    const float4* wfo = g_wfq + o * 288;
    ull S = 0, T = 0;
#pragma unroll
    for (int f = lane, k = 0; k < 9; k++, f += 32) {
        ull a = *(const ull*)&s_h2[f];
        float4 w = __ldg(wfo + f);
        ull wlo, whi;
        asm("mov.b64 %0, {%2, %3}; mov.b64 %1, {%4, %5};"
            : "=l"(wlo), "=l"(whi) : "f"(w.x), "f"(w.y), "f"(w.z), "f"(w.w));
        ffma2(S, a, wlo);   // (c*wc, s*ws)
        ffma2(T, a, whi);   // (c*ws, s*wc)
    }
    float Sx = f2lo(S) + f2hi(S);
    float Sy = f2hi(T) - f2lo(T);
#pragma unroll
    for (int off = 16; off; off >>= 1) {
        Sx += __shfl_xor_sync(0xffffffff, Sx, off);
        Sy += __shfl_xor_sync(0xffffffff, Sy, off);
    }
    if (lane == 0)
        out[(size_t)blockIdx.x * 10 + o] = Sy * fast_rsqrt(fmaxf(Sx * Sx + Sy * Sy, 1e-30f));
}

extern "C" void kernel_launch(void* const* d_in, const int* in_sizes, int n_in,
                              void* d_out, int out_size) {
    const float* x  = (const float*)d_in[0];
    const float* w1 = (const float*)d_in[1];
    const float* w2 = (const float*)d_in[2];
    const float* wf = (const float*)d_in[3];
    float* out = (float*)d_out;
    int B = in_sizes[0] / 784;
    prep_kernel<<<6, 512>>>(w1, w2, wf);
    ring_kernel<<<B, 320>>>(x, out);
}

// round 10
// speedup vs baseline: 1.2522x; 1.2000x over previous
#include <cuda_runtime.h>

typedef unsigned long long ull;

// ---- SoA weight planes ----
__device__ __align__(16) float g_w1c[16],  g_w1s[16];    // [co*4 + i*2 + j]
__device__ __align__(16) float g_w2c[544], g_w2s[544];   // [co*68 + c*16 + i*4 + j]
__device__ __align__(16) float4 g_wfq[2880];             // [o*288 + f] = (c, s, s, c)

__global__ void prep_kernel(const float* __restrict__ w1,
                            const float* __restrict__ w2,
                            const float* __restrict__ wf) {
    int gt = blockIdx.x * blockDim.x + threadIdx.x;
    for (int i = gt; i < 3408; i += gridDim.x * blockDim.x) {
        if (i < 16) {
            float s, c; sincosf(w1[i], &s, &c);
            g_w1c[i] = c; g_w1s[i] = s;
        } else if (i < 528) {
            int k = i - 16;
            int co = k >> 6, r = k & 63;
            float s, c; sincosf(w2[k], &s, &c);
            g_w2c[co * 68 + r] = c; g_w2s[co * 68 + r] = s;
        } else {
            int k = i - 528;
            int f = k / 10, o = k % 10;
            float s, c; sincosf(wf[k], &s, &c);
            g_wfq[o * 288 + f] = make_float4(c, s, s, c);
        }
    }
}

// packed dual-FMA: acc(lo,hi) += a(lo,hi) * b(lo,hi)
static __device__ __forceinline__ void ffma2(ull& acc, ull a, ull b) {
    asm("fma.rn.f32x2 %0, %1, %2, %0;" : "+l"(acc) : "l"(a), "l"(b));
}
static __device__ __forceinline__ float f2lo(ull v) { return __uint_as_float((unsigned)v); }
static __device__ __forceinline__ float f2hi(ull v) { return __uint_as_float((unsigned)(v >> 32)); }
static __device__ __forceinline__ ull pack2(float lo, float hi) {
    ull r;
    asm("mov.b64 %0, {%1, %2};" : "=l"(r) : "f"(lo), "f"(hi));
    return r;
}

// MUFU-free sincos: quadrant reduction + minimax polys
static __device__ __forceinline__ void fast_sincos(float x, float& s, float& c) {
    float t = fmaf(x, 0.63661977236758134f, 12582912.0f);
    unsigned q = __float_as_uint(t);
    float kf = t - 12582912.0f;
    float r = fmaf(kf, -1.57079625129699707031f, x);
    r = fmaf(kf, -7.54978941586159e-08f, r);
    float y = r * r;
    float ps = fmaf(y, -1.95152959e-4f, 8.33216087e-3f);
    ps = fmaf(y, ps, -1.66666546e-1f);
    float s0 = fmaf(r * y, ps, r);
    float pc = fmaf(y, 2.44331571e-5f, -1.38873162e-3f);
    pc = fmaf(y, pc, 4.16666232e-2f);
    pc = fmaf(y, pc, -0.5f);
    float c0 = fmaf(y, pc, 1.0f);
    bool sw = q & 1u;
    float ss = sw ? c0 : s0;
    float cc = sw ? s0 : c0;
    unsigned sgs = (q & 2u) << 30;
    unsigned sgc = ((q + 1u) & 2u) << 30;
    s = __uint_as_float(__float_as_uint(ss) ^ sgs);
    c = __uint_as_float(__float_as_uint(cc) ^ sgc);
}

// MUFU-free rsqrt
static __device__ __forceinline__ float fast_rsqrt(float d) {
    float y = __uint_as_float(0x5F3759DFu - (__float_as_uint(d) >> 1));
    float h = 0.5f * d;
    y = y * fmaf(-(h * y), y, 1.5f);
    y = y * fmaf(-(h * y), y, 1.5f);
    return y;
}

// h1 arena layout (floats). Bank phases chosen so even-wo (A) and odd-wo (B)
// LDS.128 groups never share banks within one instruction:
//   cA @ 0     (bank 0),  cB @ 912  (bank 16)
//   sA @ 1808  (bank 16), sB @ 2720 (bank 0)
// Pads absorb B-copy underflow writes (px<2 lands in row/region pads).
#define OFF_CA 0
#define OFF_CB 912
#define OFF_SA 1808
#define OFF_SB 2720
#define H1_TOTAL 3616

__global__ __launch_bounds__(320, 4) void ring_kernel(const float* __restrict__ x,
                                                      float* __restrict__ out) {
    __shared__ __align__(16) float s_h1[H1_TOTAL];
    __shared__ __align__(16) float2 s_h2[288];                // [(ho*6+wo)*8 + co]
    __shared__ __align__(16) float s_w2c[544], s_w2s[544];

    const int tid = threadIdx.x;

    // ---- w2 staging (consumed by stage 2, after the barrier below) ----
    for (int i = tid; i < 544; i += 320) { s_w2c[i] = g_w2c[i]; s_w2s[i] = g_w2s[i]; }

    // ---- Fused stage 0+1: conv1 2x2 s2 (non-overlapping patches) ----
    // 196 threads; each loads its own 4 pixels from global, trig, 4 co outputs.
    // w1 read straight from global (__ldg broadcast, L1-hot) -> NO race, no barrier.
    if (tid < 196) {
        int py = tid / 14, px = tid % 14;
        const float* xb = x + (size_t)blockIdx.x * 784 + py * 56 + px * 2;
        float2 p0 = *reinterpret_cast<const float2*>(xb);
        float2 p1 = *reinterpret_cast<const float2*>(xb + 28);
        float c00, s00, c01, s01, c10, s10, c11, s11;
        fast_sincos(p0.x, s00, c00);
        fast_sincos(p0.y, s01, c01);
        fast_sincos(p1.x, s10, c10);
        fast_sincos(p1.y, s11, c11);
        ull vc0 = pack2(c00, c01), vs0 = pack2(s00, s01);
        ull vc1 = pack2(c10, c11), vs1 = pack2(s10, s11);
        int dst = py * 16 + px;
        const ulonglong2* w1c = reinterpret_cast<const ulonglong2*>(g_w1c);
        const ulonglong2* w1s = reinterpret_cast<const ulonglong2*>(g_w1s);
#pragma unroll
        for (int co = 0; co < 4; co++) {
            ulonglong2 wc = __ldg(w1c + co);
            ulonglong2 ws = __ldg(w1s + co);
            ull S = 0, T3 = 0, T4 = 0;
            ffma2(S,  vc0, wc.x); ffma2(S,  vc1, wc.y);
            ffma2(S,  vs0, ws.x); ffma2(S,  vs1, ws.y);
            ffma2(T3, vs0, wc.x); ffma2(T3, vs1, wc.y);
            ffma2(T4, vc0, ws.x); ffma2(T4, vc1, ws.y);
            float Sx = f2lo(S) + f2hi(S);
            float Sy = (f2lo(T3) + f2hi(T3)) - (f2lo(T4) + f2hi(T4));
            float r = fast_rsqrt(fmaxf(Sx * Sx + Sy * Sy, 1e-30f));
            float hc = Sx * r, hs = Sy * r;
            int d = co * 224 + dst;
            s_h1[OFF_CA + d] = hc;
            s_h1[OFF_SA + d] = hs;
            s_h1[OFF_CB + d - 2] = hc;   // px<2 underflow lands in pads
            s_h1[OFF_SB + d - 2] = hs;
        }
    }
    __syncthreads();

    // ---- Stage 2: conv2 4x4 s2 -> 288 outputs; one/thread, all LDS.128 ----
    int st = tid + ((blockIdx.x & 3) << 5);   // rotate idle warp across SMSPs
    if (st >= 320) st -= 320;
    if (st < 288) {
        int co = st & 7, sp = st >> 3;        // co fastest -> broadcast in 8-lane groups
        int ho = sp / 6, wo = sp % 6;
        const float* pc = s_h1 + ((wo & 1) ? OFF_CB : OFF_CA);
        const float* ps = s_h1 + ((wo & 1) ? OFF_SB : OFF_SA);
        const int vb0 = ho * 32 + (wo & ~1) * 2;   // 16B-aligned window start
        const int wb0 = co * 68;
        ull S = 0, T3 = 0, T4 = 0;
#pragma unroll
        for (int c = 0; c < 4; c++) {
#pragma unroll
            for (int i = 0; i < 4; i++) {
                int vb = c * 224 + vb0 + i * 16;
                ulonglong2 vc = *(const ulonglong2*)&pc[vb];
                ulonglong2 vs = *(const ulonglong2*)&ps[vb];
                int wb = wb0 + c * 16 + i * 4;
                ulonglong2 wc = *(const ulonglong2*)&s_w2c[wb];
                ulonglong2 ws = *(const ulonglong2*)&s_w2s[wb];
                ffma2(S,  vc.x, wc.x); ffma2(S,  vc.y, wc.y);
                ffma2(S,  vs.x, ws.x); ffma2(S,  vs.y, ws.y);
                ffma2(T3, vs.x, wc.x); ffma2(T3, vs.y, wc.y);
                ffma2(T4, vc.x, ws.x); ffma2(T4, vc.y, ws.y);
            }
        }
        float Sx = f2lo(S) + f2hi(S);
        float Sy = (f2lo(T3) + f2hi(T3)) - (f2lo(T4) + f2hi(T4));
        float r = fast_rsqrt(fmaxf(Sx * Sx + Sy * Sy, 1e-30f));
        s_h2[st] = make_float2(Sx * r, Sy * r);
    }
    __syncthreads();

    // ---- Stage 3: FF ring, one warp per class; wf float4 from global ----
    int o = tid >> 5, lane = tid & 31;
    const float4* wfo = g_wfq + o * 288;
    ull S = 0, T = 0;
#pragma unroll
    for (int f = lane, k = 0; k < 9; k++, f += 32) {
        ull a = *(const ull*)&s_h2[f];
        float4 w = __ldg(wfo + f);
        ull wlo = pack2(w.x, w.y);
        ull whi = pack2(w.z, w.w);
        ffma2(S, a, wlo);   // (c*wc, s*ws)
        ffma2(T, a, whi);   // (c*ws, s*wc)
    }
    float Sx = f2lo(S) + f2hi(S);
    float Sy = f2hi(T) - f2lo(T);
#pragma unroll
    for (int off = 16; off; off >>= 1) {
        Sx += __shfl_xor_sync(0xffffffff, Sx, off);
        Sy += __shfl_xor_sync(0xffffffff, Sy, off);
    }
    if (lane == 0)
        out[(size_t)blockIdx.x * 10 + o] = Sy * fast_rsqrt(fmaxf(Sx * Sx + Sy * Sy, 1e-30f));
}

extern "C" void kernel_launch(void* const* d_in, const int* in_sizes, int n_in,
                              void* d_out, int out_size) {
    const float* x  = (const float*)d_in[0];
    const float* w1 = (const float*)d_in[1];
    const float* w2 = (const float*)d_in[2];
    const float* wf = (const float*)d_in[3];
    float* out = (float*)d_out;
    int B = in_sizes[0] / 784;
    prep_kernel<<<6, 512>>>(w1, w2, wf);
    ring_kernel<<<B, 320>>>(x, out);
}